// round 17
// baseline (speedup 1.0000x reference)
#include <cuda_runtime.h>
#include <cuda_fp16.h>
#include <cstdint>

// ============================================================================
// Constants
// ============================================================================
#define NCH     32          // 32 chunks of K=64
#define TM      128
#define TN      128
#define STAGES  3
#define A_STAGE_BYTES (TM * 128)                      // 16384
#define B_STAGE_BYTES (TN * 128)                      // 16384
#define STAGE_BYTES   (A_STAGE_BYTES + B_STAGE_BYTES) // 32768
#define SMEM_TOTAL    (STAGES * STAGE_BYTES)          // 98304 -> 2 CTAs/SM

// ============================================================================
// Device-global scratch
// ============================================================================
__device__ __align__(256) __half g_X[32768ull * 2048];
__device__ __align__(256) __half g_H[32768ull * 2048];
__device__ __align__(256) __half g_W1[2048ull * 2048];
__device__ __align__(256) __half g_W2[2048ull * 2048];
__device__ float g_b1[2048];
__device__ float g_b2[2048];
__device__ int   g_flag[256];    // per-mtile completion counters (layer 1 -> 2)

// ============================================================================
// Helpers
// ============================================================================
__device__ __forceinline__ uint32_t smem_to_u32(const void* p) {
    uint32_t a;
    asm("{ .reg .u64 t; cvta.to.shared.u64 t, %1; cvt.u32.u64 %0, t; }" : "=r"(a) : "l"(p));
    return a;
}

__device__ __forceinline__ unsigned swz(unsigned off) { return off ^ ((off >> 3) & 0x70); }

__device__ __forceinline__ void cp_async16(uint32_t dst, const void* src) {
    asm volatile("cp.async.cg.shared.global [%0], [%1], 16;" :: "r"(dst), "l"(src));
}

__device__ __forceinline__ void ldsm_x4(uint32_t r[4], uint32_t addr) {
    asm volatile("ldmatrix.sync.aligned.m8n8.x4.shared.b16 {%0,%1,%2,%3}, [%4];"
                 : "=r"(r[0]), "=r"(r[1]), "=r"(r[2]), "=r"(r[3]) : "r"(addr));
}

__device__ __forceinline__ void mma16816(float d[4], const uint32_t a[4], uint32_t b0, uint32_t b1) {
    asm volatile("mma.sync.aligned.m16n8k16.row.col.f32.f16.f16.f32 "
                 "{%0,%1,%2,%3}, {%4,%5,%6,%7}, {%8,%9}, {%0,%1,%2,%3};"
                 : "+f"(d[0]), "+f"(d[1]), "+f"(d[2]), "+f"(d[3])
                 : "r"(a[0]), "r"(a[1]), "r"(a[2]), "r"(a[3]), "r"(b0), "r"(b1));
}

// pack 8 fp32 -> 8 fp16 (uint4)
__device__ __forceinline__ uint4 pack8(const float* v) {
    unsigned h[4];
#pragma unroll
    for (int p = 0; p < 4; p++) {
        __half ha = __float2half_rn(v[2 * p]);
        __half hb = __float2half_rn(v[2 * p + 1]);
        h[p] = (unsigned)__half_as_ushort(ha) | ((unsigned)__half_as_ushort(hb) << 16);
    }
    return make_uint4(h[0], h[1], h[2], h[3]);
}

// ============================================================================
// Fused prep: conv_x (blocks [0,32768)) + weights/biases/flags ([32768,36864))
// ============================================================================
__global__ void prep_all_kernel(const float* __restrict__ qr, const float* __restrict__ qi,
                                const float* __restrict__ qj, const float* __restrict__ qk,
                                const float* __restrict__ w1r, const float* __restrict__ w1i,
                                const float* __restrict__ w1j, const float* __restrict__ w1k,
                                const float* __restrict__ w2r, const float* __restrict__ w2i,
                                const float* __restrict__ w2j, const float* __restrict__ w2k,
                                const float* b1r, const float* b1i, const float* b1j, const float* b1k,
                                const float* b2r, const float* b2i, const float* b2j, const float* b2k) {
    if (blockIdx.x < 32768) {
        unsigned idx = blockIdx.x * blockDim.x + threadIdx.x;
        unsigned n  = idx >> 8;
        unsigned f0 = (idx & 255u) << 3;
        unsigned comp = f0 >> 9, d0 = f0 & 511;
        const float* src = (comp == 0 ? qr : comp == 1 ? qi : comp == 2 ? qj : qk);
        const float4* s4 = (const float4*)(src + (size_t)n * 512 + d0);
        float4 a = s4[0], b = s4[1];
        float v[8] = {a.x, a.y, a.z, a.w, b.x, b.y, b.z, b.w};
        *(uint4*)(g_X + (size_t)n * 2048 + f0) = pack8(v);
    } else {
        unsigned pb = blockIdx.x - 32768;
        int layer2 = (pb >= 2048);
        // reset layer-1 -> layer-2 flags (must be zero at each graph replay)
        if (pb == 0 && threadIdx.x < 256) g_flag[threadIdx.x] = 0;

        unsigned idx = (pb & 2047u) * blockDim.x + threadIdx.x;
        unsigned o  = idx >> 8;
        unsigned i0 = (idx & 255u) << 3;
        unsigned oc = o >> 9, orow = o & 511;
        unsigned ic = i0 >> 9, ii = i0 & 511;

        const int   idxT[4][4] = {{0,1,2,3},{1,0,3,2},{2,3,0,1},{3,2,1,0}};
        const float sgnT[4][4] = {{ 1.f, 1.f, 1.f, 1.f},
                                  {-1.f, 1.f,-1.f, 1.f},
                                  {-1.f, 1.f, 1.f,-1.f},
                                  {-1.f,-1.f, 1.f, 1.f}};
        int   w = idxT[ic][oc];
        float s = sgnT[ic][oc];
        const float* W = layer2 ? (w == 0 ? w2r : w == 1 ? w2i : w == 2 ? w2j : w2k)
                                : (w == 0 ? w1r : w == 1 ? w1i : w == 2 ? w1j : w1k);
        const float4* s4 = (const float4*)(W + (size_t)orow * 512 + ii);
        float4 a = s4[0], b = s4[1];
        float v[8] = {s*a.x, s*a.y, s*a.z, s*a.w, s*b.x, s*b.y, s*b.z, s*b.w};

        __half* dst = (layer2 ? g_W2 : g_W1) + (size_t)o * 2048;
        *(uint4*)(dst + i0) = pack8(v);

        if (idx < 2048) {
            int comp = idx >> 9, d = idx & 511;
            if (layer2) g_b2[idx] = (comp == 0 ? b2r : comp == 1 ? b2i : comp == 2 ? b2j : b2k)[d];
            else        g_b1[idx] = (comp == 0 ? b1r : comp == 1 ? b1i : comp == 2 ? b1j : b1k)[d];
        }
    }
}

// ============================================================================
// FUSED two-layer GEMM. grid (16, 512):
//   blockIdx.y in [0,256)   : layer 1 tile (mtile = y*128)      -> writes g_H, signals flag
//   blockIdx.y in [256,512) : layer 2 tile (mtile = (y-256)*128) -> spins on flag, writes out
// Deadlock-free: CTAs dispatch in bid order; all layer-1 bids precede layer-2.
// GEMM mainloop = round-16 champion (cross-barrier fragment pipelining).
// ============================================================================
__global__ void __launch_bounds__(128, 2) qgemm_fused_kernel(float* __restrict__ out) {
    extern __shared__ __align__(1024) unsigned char smem[];
    uint32_t sb = smem_to_u32(smem);

    int layer2 = (blockIdx.y >= 256);
    int mt = layer2 ? (blockIdx.y - 256) : blockIdx.y;

    const __half* Ag   = layer2 ? g_H  : g_X;
    const __half* Bg   = layer2 ? g_W2 : g_W1;
    const float*  bias = layer2 ? g_b2 : g_b1;

    int tid = threadIdx.x, lane = tid & 31, warp = tid >> 5;
    int wm = warp >> 1, wn = warp & 1;
    int mtile = mt * TM, ntile = blockIdx.x * TN;

    // layer-2: wait for this mtile's 16 layer-1 producer CTAs
    if (layer2) {
        if (tid == 0) {
            int v;
            do {
                asm volatile("ld.acquire.gpu.global.s32 %0, [%1];" : "=r"(v) : "l"(&g_flag[mt]) : "memory");
                if (v < 16) __nanosleep(256);
            } while (v < 16);
        }
        __syncthreads();
    }

    float acc[4][8][4];
#pragma unroll
    for (int i = 0; i < 4; i++)
#pragma unroll
        for (int j = 0; j < 8; j++)
#pragma unroll
            for (int k = 0; k < 4; k++) acc[i][j][k] = 0.f;

    auto issue = [&](int c_) {
        if (c_ < NCH) {
            int s = c_ % STAGES;
            uint32_t st = sb + s * STAGE_BYTES;
            int kk = c_ * 64;
            const __half* ap = Ag + (size_t)mtile * 2048 + kk;
            const __half* bp = Bg + (size_t)ntile * 2048 + kk;
#pragma unroll
            for (int i = 0; i < 8; i++) {     // A: 128 rows x 128B
                int idx = tid + i * 128;
                int r = idx >> 3, in16 = idx & 7;
                uint32_t d = st + swz((unsigned)(r * 128 + in16 * 16));
                cp_async16(d, (const char*)(ap + (size_t)r * 2048) + in16 * 16);
            }
#pragma unroll
            for (int i = 0; i < 8; i++) {     // B: 128 rows x 128B
                int idx = tid + i * 128;
                int r = idx >> 3, in16 = idx & 7;
                uint32_t d = st + A_STAGE_BYTES + swz((unsigned)(r * 128 + in16 * 16));
                cp_async16(d, (const char*)(bp + (size_t)r * 2048) + in16 * 16);
            }
        }
        asm volatile("cp.async.commit_group;" ::: "memory");
    };

    auto ldA = [&](uint32_t st, int ks, uint32_t a[4][4]) {
        int arow = wm * 64 + (lane & 15);
        int akb  = ks * 32 + ((lane >> 4) << 4);
#pragma unroll
        for (int im = 0; im < 4; im++)
            ldsm_x4(a[im], st + swz((unsigned)((arow + im * 16) * 128 + akb)));
    };
    auto ldB = [&](uint32_t st, int ks, uint32_t b[4][4]) {
        int g    = lane >> 3;
        int brow = wn * 64 + (lane & 7) + ((g >> 1) << 3);
        int bkb  = ks * 32 + ((g & 1) << 4);
#pragma unroll
        for (int j = 0; j < 4; j++)
            ldsm_x4(b[j], st + A_STAGE_BYTES + swz((unsigned)((brow + j * 16) * 128 + bkb)));
    };
    auto domma = [&](uint32_t a[4][4], uint32_t b[4][4]) {
#pragma unroll
        for (int im = 0; im < 4; im++)
#pragma unroll
            for (int j = 0; j < 4; j++) {
                mma16816(acc[im][2 * j],     a[im], b[j][0], b[j][1]);
                mma16816(acc[im][2 * j + 1], a[im], b[j][2], b[j][3]);
            }
    };

    issue(0); issue(1);

    uint32_t a0[4][4], b0[4][4], a1[4][4], b1[4][4];

    // prologue: chunk 0 resident, preload its ks0 fragments
    asm volatile("cp.async.wait_group 1;" ::: "memory");
    __syncthreads();
    ldA(sb, 0, a0); ldB(sb, 0, b0);

    for (int cc = 0; cc < NCH; cc++) {
        uint32_t st = sb + (cc % STAGES) * STAGE_BYTES;

        ldA(st, 1, a1); ldB(st, 1, b1);     // ks1 frags (chunk cc resident)
        issue(cc + 2);                       // overlaps with compute below
        domma(a0, b0);                       // ks0 (preloaded last chunk)
        ldA(st, 2, a0); ldB(st, 2, b0);     // ks2
        domma(a1, b1);                       // ks1
        ldA(st, 3, a1); ldB(st, 3, b1);     // ks3
        domma(a0, b0);                       // ks2

        // publish chunk cc+1 CTA-wide
        asm volatile("cp.async.wait_group 1;" ::: "memory");
        __syncthreads();

        int cn = (cc + 1 < NCH) ? cc + 1 : cc;
        uint32_t stn = sb + (cn % STAGES) * STAGE_BYTES;
        ldA(stn, 0, a0); ldB(stn, 0, b0);   // next chunk ks0 — hides under domma
        domma(a1, b1);                       // ks3
    }

    __syncthreads();   // pipeline drained

    // ------------------------- epilogue (smem-staged) -------------------------
    if (!layer2) {
        const unsigned RB = 272;     // padded fp16 row (256B data + 16B pad)
        unsigned char* shH = smem;   // 128*272 = 34816
#pragma unroll
        for (int im = 0; im < 4; im++) {
#pragma unroll
            for (int j = 0; j < 8; j++) {
                int nl = wn * 64 + j * 8 + (lane & 3) * 2;
                int ng = ntile + nl;
                float b0f = bias[ng], b1f = bias[ng + 1];
#pragma unroll
                for (int h = 0; h < 2; h++) {
                    int ml = wm * 64 + im * 16 + h * 8 + (lane >> 2);
                    float v0 = fmaxf(acc[im][j][h * 2 + 0] + b0f, 0.f);
                    float v1 = fmaxf(acc[im][j][h * 2 + 1] + b1f, 0.f);
                    *(__half2*)(shH + (unsigned)ml * RB + (unsigned)nl * 2) =
                        __halves2half2(__float2half_rn(v0), __float2half_rn(v1));
                }
            }
        }
        __syncthreads();
        int r = tid;
        const uint4* sH = (const uint4*)(shH + (unsigned)r * RB);
        uint4* dH = (uint4*)(g_H + (size_t)(mtile + r) * 2048 + ntile);
#pragma unroll
        for (int k = 0; k < 16; k++) dH[k] = sH[k];

        // release: make H tile visible, then signal the consumer flag
        __threadfence();
        __syncthreads();
        if (tid == 0) atomicAdd(&g_flag[mt], 1);
    } else {
        const unsigned RB = 528;     // padded fp32 row
        unsigned char* shF = smem;   // 128*528 = 67584
#pragma unroll
        for (int im = 0; im < 4; im++) {
#pragma unroll
            for (int j = 0; j < 8; j++) {
                int nl = wn * 64 + j * 8 + (lane & 3) * 2;
                int ng = ntile + nl;
                float b0f = bias[ng], b1f = bias[ng + 1];
#pragma unroll
                for (int h = 0; h < 2; h++) {
                    int ml = wm * 64 + im * 16 + h * 8 + (lane >> 2);
                    float2 v;
                    v.x = acc[im][j][h * 2 + 0] + b0f;
                    v.y = acc[im][j][h * 2 + 1] + b1f;
                    *(float2*)(shF + (unsigned)ml * RB + (unsigned)nl * 4) = v;
                }
            }
        }
        __syncthreads();
        int r = tid;
        int comp = ntile >> 9, dcol = ntile & 511;
        const uint4* sF = (const uint4*)(shF + (unsigned)r * RB);
        uint4* dF = (uint4*)(out + (size_t)comp * (32768ull * 512) + (size_t)(mtile + r) * 512 + dcol);
#pragma unroll
        for (int k = 0; k < 32; k++) dF[k] = sF[k];
    }
}

// ============================================================================
// Launch
// ============================================================================
extern "C" void kernel_launch(void* const* d_in, const int* in_sizes, int n_in,
                              void* d_out, int out_size) {
    const float* qr  = (const float*)d_in[0];
    const float* qi  = (const float*)d_in[1];
    const float* qj  = (const float*)d_in[2];
    const float* qk  = (const float*)d_in[3];
    const float* w1r = (const float*)d_in[4];
    const float* w1i = (const float*)d_in[5];
    const float* w1j = (const float*)d_in[6];
    const float* w1k = (const float*)d_in[7];
    const float* w2r = (const float*)d_in[8];
    const float* w2i = (const float*)d_in[9];
    const float* w2j = (const float*)d_in[10];
    const float* w2k = (const float*)d_in[11];
    const float* b1r = (const float*)d_in[12];
    const float* b1i = (const float*)d_in[13];
    const float* b1j = (const float*)d_in[14];
    const float* b1k = (const float*)d_in[15];
    const float* b2r = (const float*)d_in[16];
    const float* b2i = (const float*)d_in[17];
    const float* b2j = (const float*)d_in[18];
    const float* b2k = (const float*)d_in[19];
    float* out = (float*)d_out;

    cudaFuncSetAttribute(qgemm_fused_kernel, cudaFuncAttributeMaxDynamicSharedMemorySize, SMEM_TOTAL);

    prep_all_kernel<<<36864, 256>>>(qr, qi, qj, qk,
                                    w1r, w1i, w1j, w1k, w2r, w2i, w2j, w2k,
                                    b1r, b1i, b1j, b1k, b2r, b2i, b2j, b2k);

    dim3 grid(16, 512);
    qgemm_fused_kernel<<<grid, 128, SMEM_TOTAL>>>(out);
}